// round 2
// baseline (speedup 1.0000x reference)
#include <cuda_runtime.h>

// Problem constants (fixed by the dataset)
#define B_  16
#define D_  128
#define T_  4096
#define K_  1024
#define BT_ (B_*T_)          // 65536 rows
#define MT  128              // row tile (t within one b)
#define NT  128              // code tile
#define NBLK_C 1024          // gather/loss blocks

// Scratch (no allocations allowed)
__device__ float  g_wnorm[K_];                 // fl32(||w_k||^2), correctly rounded
__device__ float  g_xnorm[BT_];                // fl32(||x_r||^2)
__device__ __align__(16) int g_idx[BT_];       // argmin indices
__device__ double g_part[NBLK_C];              // loss partial sums (double)

// ---------------------------------------------------------------------------
// Kernel 1: ||w_k||^2 in double, rounded once to fp32 (correctly rounded).
// One warp per code.
// ---------------------------------------------------------------------------
__global__ void wnorm_kernel(const float* __restrict__ W) {
    int k = blockIdx.x * 8 + threadIdx.y;     // gridDim.x=128, blockDim=(32,8)
    int lane = threadIdx.x;
    float4 v = *(const float4*)(W + (size_t)k * D_ + lane * 4);
    double s = (double)v.x * v.x + (double)v.y * v.y
             + (double)v.z * v.z + (double)v.w * v.w;
    #pragma unroll
    for (int o = 16; o > 0; o >>= 1) s += __shfl_down_sync(0xffffffffu, s, o);
    if (lane == 0) g_wnorm[k] = (float)s;
}

// ---------------------------------------------------------------------------
// Kernel 1b: ||x_r||^2 per row (b,t), double accumulate, round once.
// Exact reduction order is irrelevant (argmin invariant to whole-ulp shifts
// of the per-row constant), we just need a consistent fp32 value.
// ---------------------------------------------------------------------------
__global__ void xnorm_kernel(const float* __restrict__ x) {
    int r = blockIdx.x * 256 + threadIdx.x;   // 0..BT_-1
    int b = r >> 12;                          // r / T_
    int t = r & (T_ - 1);
    const float* xp = x + (size_t)b * D_ * T_ + t;
    double s = 0.0;
    #pragma unroll 8
    for (int d = 0; d < D_; d++) {
        float v = xp[(size_t)d * T_];
        s += (double)v * (double)v;
    }
    g_xnorm[r] = (float)s;
}

// ---------------------------------------------------------------------------
// Kernel 2: fused GEMM + argmin, replicating the reference fp32 arithmetic:
//   dist_k = fl( fl(||x||^2 + ||w_k||^2) - 2 * dot_k )
// where dot_k is a SINGLE-ACCUMULATOR sequential fp32 FMA over d=0..127
// (Eigen gebp order used by XLA-CPU matmul). Argmin: first index wins ties.
// Block: 256 threads = 16x16, each an 8x8 micro-tile. Tile: 128 t x 128 k.
// ---------------------------------------------------------------------------
__global__ void __launch_bounds__(256) gemm_argmin_kernel(
    const float* __restrict__ x, const float* __restrict__ W,
    float* __restrict__ out_idx_f)
{
    extern __shared__ float smem[];
    float* xs = smem;              // [D_][MT]  (d-major)
    float* ws = smem + D_ * MT;    // [D_][NT]  (d-major, transposed from W)

    const int tile = blockIdx.x;               // 0..511
    const int rows_per_b = T_ / MT;            // 32
    const int b  = tile / rows_per_b;
    const int t0 = (tile % rows_per_b) * MT;
    const int tid = threadIdx.x;
    const int ty = tid >> 4, tx = tid & 15;

    // Load x tile: x[b, d, t0 + t]  (coalesced over t)
    const float* xb = x + (size_t)b * D_ * T_ + t0;
    #pragma unroll
    for (int rep = 0; rep < 16; rep++) {
        int lin = rep * 256 + tid;             // 0..4095 float4 slots
        int d  = lin >> 5;                     // 0..127
        int t4 = lin & 31;                     // 0..31
        float4 v = *(const float4*)(xb + (size_t)d * T_ + t4 * 4);
        *(float4*)(xs + d * MT + t4 * 4) = v;
    }

    // Per-row ||x||^2 constants for this thread's 8 rows
    float arow[8];
    #pragma unroll
    for (int i = 0; i < 8; i++)
        arow[i] = g_xnorm[b * T_ + t0 + ty * 8 + i];

    float bestv[8];
    int   besti[8];
    #pragma unroll
    for (int i = 0; i < 8; i++) { bestv[i] = 3.4e38f; besti[i] = 0; }

    for (int n0 = 0; n0 < K_; n0 += NT) {
        __syncthreads();   // protect ws from previous iteration's readers
        // Load + transpose W tile: W[n0+k][d] -> ws[d][k]
        #pragma unroll
        for (int rep = 0; rep < 16; rep++) {
            int lin = rep * 256 + tid;
            int k  = lin & 127;
            int d4 = lin >> 7;                 // 0..31
            float4 v = *(const float4*)(W + (size_t)(n0 + k) * D_ + d4 * 4);
            ws[(d4 * 4 + 0) * NT + k] = v.x;
            ws[(d4 * 4 + 1) * NT + k] = v.y;
            ws[(d4 * 4 + 2) * NT + k] = v.z;
            ws[(d4 * 4 + 3) * NT + k] = v.w;
        }
        __syncthreads();

        float acc[8][8];
        #pragma unroll
        for (int i = 0; i < 8; i++)
            #pragma unroll
            for (int j = 0; j < 8; j++) acc[i][j] = 0.f;

        // Sequential fp32 FMA over d (ascending), single accumulator per
        // (i,j): replicates Eigen gebp rounding exactly.
        #pragma unroll 4
        for (int d = 0; d < D_; d++) {
            float xr[8], wr[8];
            *(float4*)(xr)     = *(const float4*)(xs + d * MT + ty * 8);
            *(float4*)(xr + 4) = *(const float4*)(xs + d * MT + ty * 8 + 4);
            *(float4*)(wr)     = *(const float4*)(ws + d * NT + tx * 8);
            *(float4*)(wr + 4) = *(const float4*)(ws + d * NT + tx * 8 + 4);
            #pragma unroll
            for (int i = 0; i < 8; i++)
                #pragma unroll
                for (int j = 0; j < 8; j++)
                    acc[i][j] = fmaf(xr[i], wr[j], acc[i][j]);
        }

        float hw[8];
        #pragma unroll
        for (int j = 0; j < 8; j++) hw[j] = g_wnorm[n0 + tx * 8 + j];
        #pragma unroll
        for (int i = 0; i < 8; i++) {
            #pragma unroll
            for (int j = 0; j < 8; j++) {
                // Reference fp32 arithmetic, step by step:
                //   s1 = fl(a + b_k);  c = 2*dot (exact);  v = fl(s1 - c)
                float s1 = __fadd_rn(arow[i], hw[j]);
                float v  = __fsub_rn(s1, 2.0f * acc[i][j]);
                // strict < : ascending k order preserves first-index tie-break
                if (v < bestv[i]) { bestv[i] = v; besti[i] = n0 + tx * 8 + j; }
            }
        }
    }

    // Cross-thread argmin reduction (16 candidates per row)
    __syncthreads();
    float* rv = smem;                        // [128][16] values
    int*   ri = (int*)(smem + 128 * 16);     // [128][16] indices
    #pragma unroll
    for (int i = 0; i < 8; i++) {
        rv[(ty * 8 + i) * 16 + tx] = bestv[i];
        ri[(ty * 8 + i) * 16 + tx] = besti[i];
    }
    __syncthreads();
    if (tid < 128) {
        float bv = rv[tid * 16];
        int   bi = ri[tid * 16];
        #pragma unroll
        for (int j = 1; j < 16; j++) {
            float v = rv[tid * 16 + j];
            int  ii = ri[tid * 16 + j];
            if (v < bv || (v == bv && ii < bi)) { bv = v; bi = ii; }
        }
        int r = b * T_ + t0 + tid;
        g_idx[r] = bi;
        out_idx_f[r] = (float)bi;
    }
}

// ---------------------------------------------------------------------------
// Kernel 3: gather quantized output (straight-through rounding replicated)
// + commitment-loss partial sums in double.
//   q = W[idx, d];  diff = fl(q - x);  out = fl(x + diff);  loss += diff^2
// ---------------------------------------------------------------------------
__global__ void __launch_bounds__(256) gather_loss_kernel(
    const float* __restrict__ x, const float* __restrict__ W,
    float* __restrict__ out)
{
    __shared__ double red[256];
    double lsum = 0.0;
    #pragma unroll
    for (int rep = 0; rep < 8; rep++) {
        size_t lin4 = (size_t)blockIdx.x * 2048 + rep * 256 + threadIdx.x;
        size_t e = lin4 * 4;                   // element offset in (B,D,T)
        size_t bd = e / T_;                    // b*D + d
        int    t  = (int)(e % T_);             // multiple of 4
        size_t b  = bd / D_;
        int    d  = (int)(bd % D_);
        int4 idx = *(const int4*)(g_idx + b * T_ + t);
        float4 xv = *(const float4*)(x + e);
        float4 q;
        q.x = W[(size_t)idx.x * D_ + d];
        q.y = W[(size_t)idx.y * D_ + d];
        q.z = W[(size_t)idx.z * D_ + d];
        q.w = W[(size_t)idx.w * D_ + d];
        float d0 = __fsub_rn(q.x, xv.x);
        float d1 = __fsub_rn(q.y, xv.y);
        float d2 = __fsub_rn(q.z, xv.z);
        float d3 = __fsub_rn(q.w, xv.w);
        float4 o;
        o.x = __fadd_rn(xv.x, d0);
        o.y = __fadd_rn(xv.y, d1);
        o.z = __fadd_rn(xv.z, d2);
        o.w = __fadd_rn(xv.w, d3);
        *(float4*)(out + e) = o;
        float s0 = __fmul_rn(d0, d0), s1 = __fmul_rn(d1, d1);
        float s2 = __fmul_rn(d2, d2), s3 = __fmul_rn(d3, d3);
        lsum += (double)s0 + (double)s1 + (double)s2 + (double)s3;
    }
    red[threadIdx.x] = lsum;
    __syncthreads();
    #pragma unroll
    for (int s = 128; s > 0; s >>= 1) {
        if (threadIdx.x < s) red[threadIdx.x] += red[threadIdx.x + s];
        __syncthreads();
    }
    if (threadIdx.x == 0) g_part[blockIdx.x] = red[0];
}

// ---------------------------------------------------------------------------
// Kernel 4: deterministic final loss reduction.
// ---------------------------------------------------------------------------
__global__ void finish_loss_kernel(float* __restrict__ out) {
    __shared__ double red[256];
    double s = 0.0;
    for (int i = threadIdx.x; i < NBLK_C; i += 256) s += g_part[i];
    red[threadIdx.x] = s;
    __syncthreads();
    #pragma unroll
    for (int st = 128; st > 0; st >>= 1) {
        if (threadIdx.x < st) red[threadIdx.x] += red[threadIdx.x + st];
        __syncthreads();
    }
    if (threadIdx.x == 0) {
        double mean = red[0] / (double)((size_t)B_ * D_ * T_);
        out[(size_t)B_ * D_ * T_ + BT_] = (float)(mean * 0.25);
    }
}

// ---------------------------------------------------------------------------
extern "C" void kernel_launch(void* const* d_in, const int* in_sizes, int n_in,
                              void* d_out, int out_size) {
    const float* x = (const float*)d_in[0];   // (B, D, T) fp32
    const float* W = (const float*)d_in[1];   // (K, D)    fp32
    float* out = (float*)d_out;               // [quantized | indices | loss]

    const int smem_bytes = 2 * D_ * MT * (int)sizeof(float);   // 128 KB
    cudaFuncSetAttribute(gemm_argmin_kernel,
                         cudaFuncAttributeMaxDynamicSharedMemorySize, smem_bytes);

    wnorm_kernel<<<K_ / 8, dim3(32, 8)>>>(W);
    xnorm_kernel<<<BT_ / 256, 256>>>(x);
    gemm_argmin_kernel<<<BT_ / MT, 256, smem_bytes>>>(x, W, out + (size_t)B_ * D_ * T_);
    gather_loss_kernel<<<NBLK_C, 256>>>(x, W, out);
    finish_loss_kernel<<<1, 256>>>(out);
}

// round 4
// speedup vs baseline: 1.5976x; 1.5976x over previous
#include <cuda_runtime.h>
#include <cuda_bf16.h>
#include <cstdint>

// Problem constants (fixed by the dataset)
#define B_  16
#define D_  128
#define T_  4096
#define K_  1024
#define BT_ (B_*T_)          // 65536 rows
#define NTILES (BT_/128)     // 512
#define NCAND 6
#define DELTA 3e-4f
#define GL_BLKS 2048
#define APITCHB 272          // smem tile row pitch in bytes (136 bf16, odd 16B chunks)

// ---------------------------------------------------------------------------
// Device scratch (no allocations allowed -> __device__ globals)
// ---------------------------------------------------------------------------
__device__ float  g_wnorm[K_];                                 // fl32(||w||^2)
__device__ float  g_xnorm[BT_];                                // fl32(||x||^2)
__device__ __align__(16) __nv_bfloat16 g_Wb[K_ * D_];          // bf16 codebook [k][d]
__device__ __align__(16) __nv_bfloat16 g_Xb[(size_t)BT_ * D_]; // bf16 x rows [r][d]
__device__ float  g_candv[BT_ * NCAND];
__device__ int    g_candk[BT_ * NCAND];
__device__ __align__(16) int g_idx[BT_];
__device__ double g_part[GL_BLKS];

__device__ __forceinline__ uint32_t smem_u32(const void* p) {
    uint32_t a;
    asm("{ .reg .u64 t; cvta.to.shared.u64 t, %1; cvt.u32.u64 %0, t; }" : "=r"(a) : "l"(p));
    return a;
}

// maintain ascending top-6 (strict < keeps earlier/lower-k entry on ties)
__device__ __forceinline__ void insert6(float v, int k, float* cv, int* ck) {
    if (v < cv[5]) {
        cv[5] = v; ck[5] = k;
        #pragma unroll
        for (int a = 5; a > 0; a--) {
            bool sw = cv[a] < cv[a - 1];
            float tv = sw ? cv[a] : cv[a - 1];
            float tu = sw ? cv[a - 1] : cv[a];
            int   tk = sw ? ck[a] : ck[a - 1];
            int   tl = sw ? ck[a - 1] : ck[a];
            cv[a - 1] = tv; cv[a] = tu;
            ck[a - 1] = tk; ck[a] = tl;
        }
    }
}

// ---------------------------------------------------------------------------
// Kernel 1: ||w||^2 (fp64->fp32, correctly rounded) + bf16 codebook.
// ---------------------------------------------------------------------------
__global__ void prep_w_kernel(const float* __restrict__ W) {
    int k = blockIdx.x * 8 + threadIdx.y;
    int lane = threadIdx.x;
    float4 v = *(const float4*)(W + (size_t)k * D_ + lane * 4);
    __nv_bfloat16 b4[4] = { __float2bfloat16(v.x), __float2bfloat16(v.y),
                            __float2bfloat16(v.z), __float2bfloat16(v.w) };
    *(uint2*)(g_Wb + (size_t)k * D_ + lane * 4) = *(uint2*)b4;
    double s = (double)v.x * v.x + (double)v.y * v.y
             + (double)v.z * v.z + (double)v.w * v.w;
    #pragma unroll
    for (int o = 16; o > 0; o >>= 1) s += __shfl_down_sync(0xffffffffu, s, o);
    if (lane == 0) g_wnorm[k] = (float)s;
}

// ---------------------------------------------------------------------------
// Kernel 2: per-tile x transpose -> bf16 rows g_Xb[r][d], plus ||x||^2.
// ---------------------------------------------------------------------------
__global__ void __launch_bounds__(256) prep_x_kernel(const float* __restrict__ x) {
    extern __shared__ float xs[];               // [128 d][128 t]
    int tid = threadIdx.x;
    int tile = blockIdx.x;
    int b = tile >> 5;
    int t0 = (tile & 31) * 128;
    int r0 = tile * 128;
    const float* xb = x + (size_t)b * D_ * T_ + t0;
    #pragma unroll
    for (int rep = 0; rep < 16; rep++) {
        int lin = rep * 256 + tid;
        int d = lin >> 5, t4 = lin & 31;
        *(float4*)(xs + d * 128 + t4 * 4) = *(const float4*)(xb + (size_t)d * T_ + t4 * 4);
    }
    __syncthreads();
    if (tid < 128) {
        double s = 0.0;
        #pragma unroll 8
        for (int d = 0; d < D_; d++) { float v = xs[d * 128 + tid]; s += (double)v * (double)v; }
        g_xnorm[r0 + tid] = (float)s;
    }
    #pragma unroll
    for (int rep = 0; rep < 8; rep++) {
        int c = (tid >> 5) + (rep & 1) * 8;      // 16B chunk within row (0..15)
        int m = (tid & 31) + (rep >> 1) * 32;    // row
        __nv_bfloat16 tmp[8];
        #pragma unroll
        for (int j = 0; j < 8; j++) tmp[j] = __float2bfloat16(xs[(c * 8 + j) * 128 + m]);
        *(uint4*)(g_Xb + (size_t)(r0 + m) * D_ + c * 8) = *(uint4*)tmp;
    }
}

// ---------------------------------------------------------------------------
// Kernel 3: HMMA (mma.sync bf16) pass-1: approx scores + per-row top-6.
// CTA: 256 threads = 8 warps x 16 rows = 128 rows; all 1024 codes in 8 k-tiles.
// A = x rows [m][d] (row-major), B = W tile [n][d] (= col-major k x n).
// smem: sA 34816 | sB 34816 (reused as merge buf) | wns 4096  => 73728 B
// ---------------------------------------------------------------------------
__global__ void __launch_bounds__(256) hmma_pass1_kernel() {
    extern __shared__ char smem[];
    char* sA = smem;
    char* sB = smem + 34816;
    float* wns = (float*)(smem + 69632);
    int tid = threadIdx.x;
    int warp = tid >> 5, lane = tid & 31;
    int r0 = blockIdx.x * 128;

    #pragma unroll
    for (int i = 0; i < 4; i++) wns[i * 256 + tid] = g_wnorm[i * 256 + tid];

    // stage A tile (128 rows x 128 bf16, pitch 272B)
    const uint4* ga = (const uint4*)(g_Xb + (size_t)r0 * D_);
    #pragma unroll
    for (int i = 0; i < 8; i++) {
        int s = i * 256 + tid;
        int row = s >> 4, c = s & 15;
        *(uint4*)(sA + row * APITCHB + c * 16) = ga[s];
    }

    // ldmatrix lane addresses
    uint32_t sAu = smem_u32(sA), sBu = smem_u32(sB);
    uint32_t aAddr = sAu + (warp * 16 + (lane & 15)) * APITCHB + (lane >> 4) * 16;
    uint32_t bRowOff = ((lane & 7) + (lane >> 4) * 8) * APITCHB + ((lane >> 3) & 1) * 16;

    float cv[2][NCAND]; int ck[2][NCAND];
    #pragma unroll
    for (int a = 0; a < NCAND; a++) {
        cv[0][a] = 3.4e38f; cv[1][a] = 3.4e38f; ck[0][a] = 0; ck[1][a] = 0;
    }

    for (int kt = 0; kt < 8; kt++) {
        __syncthreads();   // previous iteration's readers done before overwrite
        const uint4* gb = (const uint4*)(g_Wb + (size_t)kt * 128 * D_);
        #pragma unroll
        for (int i = 0; i < 8; i++) {
            int s = i * 256 + tid;
            int row = s >> 4, c = s & 15;
            *(uint4*)(sB + row * APITCHB + c * 16) = gb[s];
        }
        __syncthreads();

        float acc[16][4];
        #pragma unroll
        for (int nt = 0; nt < 16; nt++)
            #pragma unroll
            for (int q = 0; q < 4; q++) acc[nt][q] = 0.f;

        #pragma unroll
        for (int ks = 0; ks < 8; ks++) {
            uint32_t a0, a1, a2, a3;
            asm volatile("ldmatrix.sync.aligned.m8n8.x4.shared.b16 {%0,%1,%2,%3}, [%4];"
                : "=r"(a0), "=r"(a1), "=r"(a2), "=r"(a3) : "r"(aAddr + ks * 32));
            #pragma unroll
            for (int np = 0; np < 8; np++) {
                uint32_t b0, b1, b2, b3;
                uint32_t baddr = sBu + np * 16 * APITCHB + ks * 32 + bRowOff;
                asm volatile("ldmatrix.sync.aligned.m8n8.x4.shared.b16 {%0,%1,%2,%3}, [%4];"
                    : "=r"(b0), "=r"(b1), "=r"(b2), "=r"(b3) : "r"(baddr));
                asm volatile("mma.sync.aligned.m16n8k16.row.col.f32.bf16.bf16.f32 "
                    "{%0,%1,%2,%3}, {%4,%5,%6,%7}, {%8,%9}, {%0,%1,%2,%3};"
                    : "+f"(acc[np*2][0]), "+f"(acc[np*2][1]), "+f"(acc[np*2][2]), "+f"(acc[np*2][3])
                    : "r"(a0), "r"(a1), "r"(a2), "r"(a3), "r"(b0), "r"(b1));
                asm volatile("mma.sync.aligned.m16n8k16.row.col.f32.bf16.bf16.f32 "
                    "{%0,%1,%2,%3}, {%4,%5,%6,%7}, {%8,%9}, {%0,%1,%2,%3};"
                    : "+f"(acc[np*2+1][0]), "+f"(acc[np*2+1][1]), "+f"(acc[np*2+1][2]), "+f"(acc[np*2+1][3])
                    : "r"(a0), "r"(a1), "r"(a2), "r"(a3), "r"(b2), "r"(b3));
            }
        }

        // scores: v = wn_k - 2*dot.  thread owns rows (lane>>2) and +8,
        // codes k = kt*128 + nt*8 + 2*(lane&3) + {0,1}
        #pragma unroll
        for (int nt = 0; nt < 16; nt++) {
            int k0 = kt * 128 + nt * 8 + 2 * (lane & 3);
            float2 wnp = *(const float2*)(wns + k0);
            insert6(fmaf(-2.0f, acc[nt][0], wnp.x), k0,     cv[0], ck[0]);
            insert6(fmaf(-2.0f, acc[nt][1], wnp.y), k0 + 1, cv[0], ck[0]);
            insert6(fmaf(-2.0f, acc[nt][2], wnp.x), k0,     cv[1], ck[1]);
            insert6(fmaf(-2.0f, acc[nt][3], wnp.y), k0 + 1, cv[1], ck[1]);
        }
    }

    // merge 4 threads x 2 lists per row -> top-6 per row (reuse sB)
    __syncthreads();
    float* mv = (float*)sB;                      // [128][24]
    int*   mk = (int*)(sB + 128 * 24 * 4);       // [128][24]
    int rlo = warp * 16 + (lane >> 2);
    int q = lane & 3;
    #pragma unroll
    for (int a = 0; a < NCAND; a++) {
        mv[rlo * 24 + q * 6 + a] = cv[0][a];  mk[rlo * 24 + q * 6 + a] = ck[0][a];
        mv[(rlo + 8) * 24 + q * 6 + a] = cv[1][a];  mk[(rlo + 8) * 24 + q * 6 + a] = ck[1][a];
    }
    __syncthreads();
    if (tid < 128) {
        float bv[NCAND]; int bk[NCAND];
        #pragma unroll
        for (int a = 0; a < NCAND; a++) { bv[a] = 3.4e38f; bk[a] = 0; }
        #pragma unroll
        for (int i = 0; i < 24; i++)
            insert6(mv[tid * 24 + i], mk[tid * 24 + i], bv, bk);
        int r = r0 + tid;
        #pragma unroll
        for (int a = 0; a < NCAND; a++) {
            g_candv[r * NCAND + a] = bv[a];
            g_candk[r * NCAND + a] = bk[a];
        }
    }
}

// ---------------------------------------------------------------------------
// Kernel 4: exact resolve — reference fp32 arithmetic on candidates:
//   dist = fl( fl(||x||^2 + ||w||^2) - 2*dot_seq ), sequential fp32 FMA over d.
// ---------------------------------------------------------------------------
__global__ void __launch_bounds__(128) pass2_kernel(const float* __restrict__ x,
        const float* __restrict__ W, float* __restrict__ out_idx_f) {
    extern __shared__ float xs[];               // [128 d][128 t]
    int tid = threadIdx.x;
    int tile = blockIdx.x;
    int b = tile >> 5, t0 = (tile & 31) * 128, r0 = tile * 128;
    const float* xb = x + (size_t)b * D_ * T_ + t0;
    #pragma unroll
    for (int rep = 0; rep < 32; rep++) {
        int lin = rep * 128 + tid;
        int d = lin >> 5, t4 = lin & 31;
        *(float4*)(xs + d * 128 + t4 * 4) = *(const float4*)(xb + (size_t)d * T_ + t4 * 4);
    }
    __syncthreads();
    int r = r0 + tid;
    float xn = g_xnorm[r];
    float cv[NCAND]; int ck[NCAND];
    #pragma unroll
    for (int a = 0; a < NCAND; a++) { cv[a] = g_candv[r * NCAND + a]; ck[a] = g_candk[r * NCAND + a]; }
    float lim = cv[0] + DELTA;
    float bv = 3.4e38f; int bi = 0x7fffffff;
    if (cv[NCAND - 1] <= lim) {
        // candidate-list overflow (p ~ 0): exact full scan, ascending k
        for (int k = 0; k < K_; k++) {
            float acc = 0.f;
            const float* w = W + (size_t)k * D_;
            for (int d = 0; d < D_; d++) acc = fmaf(xs[d * 128 + tid], w[d], acc);
            float v = __fsub_rn(__fadd_rn(xn, g_wnorm[k]), 2.0f * acc);
            if (v < bv) { bv = v; bi = k; }
        }
    } else {
        #pragma unroll
        for (int a = 0; a < NCAND; a++) {
            if (cv[a] <= lim) {
                int k = ck[a];
                float acc = 0.f;
                const float* w = W + (size_t)k * D_;
                #pragma unroll 8
                for (int d = 0; d < D_; d++) acc = fmaf(xs[d * 128 + tid], w[d], acc);
                float v = __fsub_rn(__fadd_rn(xn, g_wnorm[k]), 2.0f * acc);
                if (v < bv || (v == bv && k < bi)) { bv = v; bi = k; }
            }
        }
    }
    g_idx[r] = bi;
    out_idx_f[r] = (float)bi;
}

// ---------------------------------------------------------------------------
// Kernel 5: coalesced gather (smem transpose) + ST rounding + loss partials.
// ---------------------------------------------------------------------------
__global__ void __launch_bounds__(256) gather_loss_kernel(const float* __restrict__ x,
        const float* __restrict__ W, float* __restrict__ out) {
    __shared__ float qs[32 * 133];
    __shared__ int idxs[32];
    __shared__ double red[256];
    int tid = threadIdx.x;
    int r0 = blockIdx.x * 32;
    int b = r0 >> 12, t0 = r0 & (T_ - 1);
    if (tid < 32) idxs[tid] = g_idx[r0 + tid];
    __syncthreads();
    #pragma unroll
    for (int rep = 0; rep < 4; rep++) {
        int s = rep * 256 + tid;
        int row = s >> 5, c4 = s & 31;
        float4 q = *(const float4*)(W + (size_t)idxs[row] * D_ + c4 * 4);
        qs[row * 133 + c4 * 4 + 0] = q.x;
        qs[row * 133 + c4 * 4 + 1] = q.y;
        qs[row * 133 + c4 * 4 + 2] = q.z;
        qs[row * 133 + c4 * 4 + 3] = q.w;
    }
    __syncthreads();
    double lsum = 0.0;
    int t = tid & 31, d0 = tid >> 5;
    #pragma unroll
    for (int p = 0; p < 16; p++) {
        int d = d0 + p * 8;
        size_t e = ((size_t)b * D_ + d) * T_ + t0 + t;
        float xv = x[e];
        float q = qs[t * 133 + d];
        float df = __fsub_rn(q, xv);
        out[e] = __fadd_rn(xv, df);              // straight-through rounding
        float sq = __fmul_rn(df, df);
        lsum += (double)sq;
    }
    red[tid] = lsum;
    __syncthreads();
    #pragma unroll
    for (int s = 128; s > 0; s >>= 1) {
        if (tid < s) red[tid] += red[tid + s];
        __syncthreads();
    }
    if (tid == 0) g_part[blockIdx.x] = red[0];
}

// ---------------------------------------------------------------------------
// Kernel 6: final loss reduction
// ---------------------------------------------------------------------------
__global__ void finish_loss_kernel(float* __restrict__ out) {
    __shared__ double red[256];
    double s = 0.0;
    for (int i = threadIdx.x; i < GL_BLKS; i += 256) s += g_part[i];
    red[threadIdx.x] = s;
    __syncthreads();
    #pragma unroll
    for (int st = 128; st > 0; st >>= 1) {
        if (threadIdx.x < st) red[threadIdx.x] += red[threadIdx.x + st];
        __syncthreads();
    }
    if (threadIdx.x == 0) {
        double mean = red[0] / (double)((size_t)B_ * D_ * T_);
        out[(size_t)B_ * D_ * T_ + BT_] = (float)(mean * 0.25);
    }
}

// ---------------------------------------------------------------------------
extern "C" void kernel_launch(void* const* d_in, const int* in_sizes, int n_in,
                              void* d_out, int out_size) {
    const float* x = (const float*)d_in[0];   // (B, D, T) fp32
    const float* W = (const float*)d_in[1];   // (K, D)    fp32
    float* out = (float*)d_out;               // [quantized | indices | loss]

    cudaFuncSetAttribute(prep_x_kernel, cudaFuncAttributeMaxDynamicSharedMemorySize, 65536);
    cudaFuncSetAttribute(hmma_pass1_kernel, cudaFuncAttributeMaxDynamicSharedMemorySize, 73728);
    cudaFuncSetAttribute(pass2_kernel, cudaFuncAttributeMaxDynamicSharedMemorySize, 65536);

    prep_w_kernel<<<K_ / 8, dim3(32, 8)>>>(W);
    prep_x_kernel<<<NTILES, 256, 65536>>>(x);
    hmma_pass1_kernel<<<NTILES, 256, 73728>>>();
    pass2_kernel<<<NTILES, 128, 65536>>>(x, W, out + (size_t)B_ * D_ * T_);
    gather_loss_kernel<<<GL_BLKS, 256>>>(x, W, out);
    finish_loss_kernel<<<1, 256>>>(out);
}

// round 5
// speedup vs baseline: 1.6437x; 1.0288x over previous
#include <cuda_runtime.h>
#include <cuda_bf16.h>
#include <cstdint>

// Problem constants (fixed by the dataset)
#define B_  16
#define D_  128
#define T_  4096
#define K_  1024
#define BT_ (B_*T_)          // 65536 rows
#define NTILES (BT_/128)     // 512
#define NCAND 6
#define DELTA 3e-4f
#define APITCHB 272          // smem MMA tile row pitch (136 bf16)

// ---------------------------------------------------------------------------
// Device scratch
// ---------------------------------------------------------------------------
__device__ float  g_wnorm[K_];                           // fl32(||w||^2)
__device__ __align__(16) __nv_bfloat16 g_Wb[K_ * D_];    // bf16 codebook [k][d]
__device__ float  g_candv[BT_ * NCAND];
__device__ int    g_candk[BT_ * NCAND];
__device__ double g_part[NTILES];

__device__ __forceinline__ uint32_t smem_u32(const void* p) {
    uint32_t a;
    asm("{ .reg .u64 t; cvta.to.shared.u64 t, %1; cvt.u32.u64 %0, t; }" : "=r"(a) : "l"(p));
    return a;
}

// ascending top-6 (strict < keeps earlier/lower-k entry on ties)
__device__ __forceinline__ void insert6(float v, int k, float* cv, int* ck) {
    if (v < cv[5]) {
        cv[5] = v; ck[5] = k;
        #pragma unroll
        for (int a = 5; a > 0; a--) {
            bool sw = cv[a] < cv[a - 1];
            float tv = sw ? cv[a] : cv[a - 1];
            float tu = sw ? cv[a - 1] : cv[a];
            int   tk = sw ? ck[a] : ck[a - 1];
            int   tl = sw ? ck[a - 1] : ck[a];
            cv[a - 1] = tv; cv[a] = tu;
            ck[a - 1] = tk; ck[a] = tl;
        }
    }
}

// ---------------------------------------------------------------------------
// Kernel 1: ||w||^2 (fp64->fp32, correctly rounded) + bf16 codebook.
// ---------------------------------------------------------------------------
__global__ void prep_w_kernel(const float* __restrict__ W) {
    int k = blockIdx.x * 8 + threadIdx.y;
    int lane = threadIdx.x;
    float4 v = *(const float4*)(W + (size_t)k * D_ + lane * 4);
    __nv_bfloat16 b4[4] = { __float2bfloat16(v.x), __float2bfloat16(v.y),
                            __float2bfloat16(v.z), __float2bfloat16(v.w) };
    *(uint2*)(g_Wb + (size_t)k * D_ + lane * 4) = *(uint2*)b4;
    double s = (double)v.x * v.x + (double)v.y * v.y
             + (double)v.z * v.z + (double)v.w * v.w;
    #pragma unroll
    for (int o = 16; o > 0; o >>= 1) s += __shfl_down_sync(0xffffffffu, s, o);
    if (lane == 0) g_wnorm[k] = (float)s;
}

// ---------------------------------------------------------------------------
// Kernel 2: HMMA pass-1 (fused x->bf16 conversion): approx scores + top-6.
// 128 threads = 4 warps x 32 rows. 8 k-tiles of 128 codes.
// smem: sA[128x272] | region2{ xs fp32 staging -> sB[128x272] + wns[1024] }
// ---------------------------------------------------------------------------
#define SM1_A   0
#define SM1_R2  34816
#define SM1_TOT (34816 + 65536)

__global__ void __launch_bounds__(128, 2) hmma_pass1_kernel(const float* __restrict__ x) {
    extern __shared__ char smem[];
    char* sA = smem + SM1_A;
    char* r2 = smem + SM1_R2;
    float* xs  = (float*)r2;                    // [128 d][128 t] (staging)
    char*  sB  = r2;                            // [128 n][272B]  (after convert)
    float* wns = (float*)(r2 + 34816);          // [1024]
    int tid = threadIdx.x;
    int warp = tid >> 5, lane = tid & 31;
    int blk = blockIdx.x;
    int b = blk >> 5, t0 = (blk & 31) * 128, r0 = blk * 128;

    // --- stage x tile fp32 (coalesced along t) ---
    const float* xb = x + (size_t)b * D_ * T_ + t0;
    #pragma unroll
    for (int i = 0; i < 32; i++) {
        int lin = i * 128 + tid;
        int d = lin >> 5, t4 = lin & 31;
        *(float4*)(xs + d * 128 + t4 * 4) = *(const float4*)(xb + (size_t)d * T_ + t4 * 4);
    }
    __syncthreads();
    // --- transpose-convert to bf16 A tile: sA[row=t][d] ---
    #pragma unroll
    for (int c = 0; c < 16; c++) {
        int m = tid;
        __nv_bfloat16 tmp[8];
        #pragma unroll
        for (int j = 0; j < 8; j++) tmp[j] = __float2bfloat16(xs[(c * 8 + j) * 128 + m]);
        *(uint4*)(sA + m * APITCHB + c * 16) = *(uint4*)tmp;
    }
    __syncthreads();
    // --- wns (xs region now dead above sB) ---
    #pragma unroll
    for (int i = 0; i < 8; i++) wns[i * 128 + tid] = g_wnorm[i * 128 + tid];

    uint32_t sAu = smem_u32(sA), sBu = smem_u32(sB);
    uint32_t aBase = sAu + (warp * 32 + (lane & 15)) * APITCHB + (lane >> 4) * 16;
    uint32_t bRowOff = ((lane & 7) + (lane >> 4) * 8) * APITCHB + ((lane >> 3) & 1) * 16;

    float cv[4][NCAND]; int ck[4][NCAND];
    #pragma unroll
    for (int l = 0; l < 4; l++)
        #pragma unroll
        for (int a = 0; a < NCAND; a++) { cv[l][a] = 3.4e38f; ck[l][a] = 0; }

    for (int kt = 0; kt < 8; kt++) {
        __syncthreads();   // prev readers of sB done
        const uint4* gb = (const uint4*)(g_Wb + (size_t)kt * 128 * D_);
        #pragma unroll
        for (int i = 0; i < 16; i++) {
            int s = i * 128 + tid;
            int row = s >> 4, c = s & 15;
            *(uint4*)(sB + row * APITCHB + c * 16) = gb[s];
        }
        __syncthreads();

        float acc[2][16][4];
        #pragma unroll
        for (int mt = 0; mt < 2; mt++)
            #pragma unroll
            for (int nt = 0; nt < 16; nt++)
                #pragma unroll
                for (int q = 0; q < 4; q++) acc[mt][nt][q] = 0.f;

        #pragma unroll
        for (int ks = 0; ks < 8; ks++) {
            uint32_t a0[4], a1[4];
            asm volatile("ldmatrix.sync.aligned.m8n8.x4.shared.b16 {%0,%1,%2,%3}, [%4];"
                : "=r"(a0[0]), "=r"(a0[1]), "=r"(a0[2]), "=r"(a0[3])
                : "r"(aBase + ks * 32));
            asm volatile("ldmatrix.sync.aligned.m8n8.x4.shared.b16 {%0,%1,%2,%3}, [%4];"
                : "=r"(a1[0]), "=r"(a1[1]), "=r"(a1[2]), "=r"(a1[3])
                : "r"(aBase + 16 * APITCHB + ks * 32));
            #pragma unroll
            for (int np = 0; np < 8; np++) {
                uint32_t b0, b1, b2, b3;
                uint32_t baddr = sBu + np * 16 * APITCHB + ks * 32 + bRowOff;
                asm volatile("ldmatrix.sync.aligned.m8n8.x4.shared.b16 {%0,%1,%2,%3}, [%4];"
                    : "=r"(b0), "=r"(b1), "=r"(b2), "=r"(b3) : "r"(baddr));
                asm volatile("mma.sync.aligned.m16n8k16.row.col.f32.bf16.bf16.f32 "
                    "{%0,%1,%2,%3}, {%4,%5,%6,%7}, {%8,%9}, {%0,%1,%2,%3};"
                    : "+f"(acc[0][np*2][0]), "+f"(acc[0][np*2][1]), "+f"(acc[0][np*2][2]), "+f"(acc[0][np*2][3])
                    : "r"(a0[0]), "r"(a0[1]), "r"(a0[2]), "r"(a0[3]), "r"(b0), "r"(b1));
                asm volatile("mma.sync.aligned.m16n8k16.row.col.f32.bf16.bf16.f32 "
                    "{%0,%1,%2,%3}, {%4,%5,%6,%7}, {%8,%9}, {%0,%1,%2,%3};"
                    : "+f"(acc[0][np*2+1][0]), "+f"(acc[0][np*2+1][1]), "+f"(acc[0][np*2+1][2]), "+f"(acc[0][np*2+1][3])
                    : "r"(a0[0]), "r"(a0[1]), "r"(a0[2]), "r"(a0[3]), "r"(b2), "r"(b3));
                asm volatile("mma.sync.aligned.m16n8k16.row.col.f32.bf16.bf16.f32 "
                    "{%0,%1,%2,%3}, {%4,%5,%6,%7}, {%8,%9}, {%0,%1,%2,%3};"
                    : "+f"(acc[1][np*2][0]), "+f"(acc[1][np*2][1]), "+f"(acc[1][np*2][2]), "+f"(acc[1][np*2][3])
                    : "r"(a1[0]), "r"(a1[1]), "r"(a1[2]), "r"(a1[3]), "r"(b0), "r"(b1));
                asm volatile("mma.sync.aligned.m16n8k16.row.col.f32.bf16.bf16.f32 "
                    "{%0,%1,%2,%3}, {%4,%5,%6,%7}, {%8,%9}, {%0,%1,%2,%3};"
                    : "+f"(acc[1][np*2+1][0]), "+f"(acc[1][np*2+1][1]), "+f"(acc[1][np*2+1][2]), "+f"(acc[1][np*2+1][3])
                    : "r"(a1[0]), "r"(a1[1]), "r"(a1[2]), "r"(a1[3]), "r"(b2), "r"(b3));
            }
        }

        // scores: v = wn_k - 2*dot. lists: [mt*2+h], rows warp*32+mt*16+h*8+(lane>>2)
        #pragma unroll
        for (int mt = 0; mt < 2; mt++) {
            #pragma unroll
            for (int nt = 0; nt < 16; nt++) {
                int k0 = kt * 128 + nt * 8 + 2 * (lane & 3);
                float2 wnp = *(const float2*)(wns + k0);
                insert6(fmaf(-2.0f, acc[mt][nt][0], wnp.x), k0,     cv[mt*2],   ck[mt*2]);
                insert6(fmaf(-2.0f, acc[mt][nt][1], wnp.y), k0 + 1, cv[mt*2],   ck[mt*2]);
                insert6(fmaf(-2.0f, acc[mt][nt][2], wnp.x), k0,     cv[mt*2+1], ck[mt*2+1]);
                insert6(fmaf(-2.0f, acc[mt][nt][3], wnp.y), k0 + 1, cv[mt*2+1], ck[mt*2+1]);
            }
        }
    }

    // merge 4 threads per row -> top-6 per row (reuse region2)
    __syncthreads();
    float* mv = (float*)r2;                      // [128][24]
    int*   mk = (int*)(r2 + 128 * 24 * 4);       // [128][24]
    #pragma unroll
    for (int mt = 0; mt < 2; mt++)
        #pragma unroll
        for (int h = 0; h < 2; h++) {
            int row = warp * 32 + mt * 16 + h * 8 + (lane >> 2);
            int q = lane & 3;
            #pragma unroll
            for (int a = 0; a < NCAND; a++) {
                mv[row * 24 + q * 6 + a] = cv[mt*2+h][a];
                mk[row * 24 + q * 6 + a] = ck[mt*2+h][a];
            }
        }
    __syncthreads();
    {
        float bv[NCAND]; int bk[NCAND];
        #pragma unroll
        for (int a = 0; a < NCAND; a++) { bv[a] = 3.4e38f; bk[a] = 0; }
        #pragma unroll
        for (int i = 0; i < 24; i++)
            insert6(mv[tid * 24 + i], mk[tid * 24 + i], bv, bk);
        int r = r0 + tid;
        #pragma unroll
        for (int a = 0; a < NCAND; a++) {
            g_candv[r * NCAND + a] = bv[a];
            g_candk[r * NCAND + a] = bk[a];
        }
    }
}

// ---------------------------------------------------------------------------
// Kernel 3: fused exact-resolve + gather + output + loss partials. 256 thr.
//   xnorm (double->fp32), dist = fl(fl(xn+wn) - 2*dot_seq) on candidates,
//   out[b,d,t] = fl(x + fl(W[bi,d] - x)), loss partial sum.
// smem: xs[128d][132] | qs[128d][133 t] | idxs[128] | red[256 dbl]
// ---------------------------------------------------------------------------
#define SM3_XS   0
#define SM3_QS   67584
#define SM3_IDX  (67584 + 68096)
#define SM3_RED  (SM3_IDX + 512)
#define SM3_TOT  (SM3_RED + 2048)

__global__ void __launch_bounds__(256) pass2_fused_kernel(const float* __restrict__ x,
        const float* __restrict__ W, float* __restrict__ out, float* __restrict__ out_idx_f) {
    extern __shared__ char smem[];
    float* xs = (float*)(smem + SM3_XS);     // [d][132]
    float* qs = (float*)(smem + SM3_QS);     // [d][133]
    int* idxs = (int*)(smem + SM3_IDX);
    double* red = (double*)(smem + SM3_RED);
    int tid = threadIdx.x;
    int blk = blockIdx.x;
    int b = blk >> 5, t0 = (blk & 31) * 128, r0 = blk * 128;

    const float* xb = x + (size_t)b * D_ * T_ + t0;
    #pragma unroll
    for (int i = 0; i < 16; i++) {
        int lin = i * 256 + tid;
        int d = lin >> 5, t4 = lin & 31;
        *(float4*)(xs + d * 132 + t4 * 4) = *(const float4*)(xb + (size_t)d * T_ + t4 * 4);
    }
    __syncthreads();

    if (tid < 128) {
        int t = tid, r = r0 + tid;
        // xnorm: double accumulate, round once (whole-ulp-shift invariant)
        double sn = 0.0;
        #pragma unroll 8
        for (int d = 0; d < D_; d++) { float v = xs[d * 132 + t]; sn += (double)v * (double)v; }
        float xn = (float)sn;

        float cvl[NCAND]; int ckl[NCAND];
        #pragma unroll
        for (int a = 0; a < NCAND; a++) { cvl[a] = g_candv[r * NCAND + a]; ckl[a] = g_candk[r * NCAND + a]; }
        float lim = cvl[0] + DELTA;
        float bv = 3.4e38f; int bi = 0x7fffffff;
        if (cvl[NCAND - 1] <= lim) {
            // overflow (p~0): exact full scan, ascending k
            for (int k = 0; k < K_; k++) {
                float acc = 0.f;
                const float* w = W + (size_t)k * D_;
                for (int d = 0; d < D_; d++) acc = fmaf(xs[d * 132 + t], w[d], acc);
                float v = __fsub_rn(__fadd_rn(xn, g_wnorm[k]), 2.0f * acc);
                if (v < bv) { bv = v; bi = k; }
            }
        } else {
            #pragma unroll
            for (int a = 0; a < NCAND; a++) {
                if (cvl[a] <= lim) {
                    int k = ckl[a];
                    float acc = 0.f;
                    const float* w = W + (size_t)k * D_;
                    #pragma unroll 8
                    for (int d = 0; d < D_; d++) acc = fmaf(xs[d * 132 + t], w[d], acc);
                    float v = __fsub_rn(__fadd_rn(xn, g_wnorm[k]), 2.0f * acc);
                    if (v < bv || (v == bv && k < bi)) { bv = v; bi = k; }
                }
            }
        }
        idxs[t] = bi;
        out_idx_f[r] = (float)bi;
    }
    __syncthreads();

    // gather W rows -> qs[d][t]  (lanes vary row -> conflict-free smem writes)
    #pragma unroll
    for (int i = 0; i < 16; i++) {
        int s = i * 256 + tid;            // 0..4095
        int row = s & 127, c4 = s >> 7;   // c4 0..31
        float4 q = *(const float4*)(W + (size_t)idxs[row] * D_ + c4 * 4);
        qs[(c4 * 4 + 0) * 133 + row] = q.x;
        qs[(c4 * 4 + 1) * 133 + row] = q.y;
        qs[(c4 * 4 + 2) * 133 + row] = q.z;
        qs[(c4 * 4 + 3) * 133 + row] = q.w;
    }
    __syncthreads();

    // write out (coalesced along t) + loss
    double lsum = 0.0;
    int t = tid & 127, dg = tid >> 7;
    float* ob = out + (size_t)b * D_ * T_ + t0;
    #pragma unroll 8
    for (int p = 0; p < 64; p++) {
        int d = dg * 64 + p;
        float xv = xs[d * 132 + t];
        float q  = qs[d * 133 + t];
        float df = __fsub_rn(q, xv);
        ob[(size_t)d * T_ + t] = __fadd_rn(xv, df);
        float sq = __fmul_rn(df, df);
        lsum += (double)sq;
    }
    red[tid] = lsum;
    __syncthreads();
    #pragma unroll
    for (int s = 128; s > 0; s >>= 1) {
        if (tid < s) red[tid] += red[tid + s];
        __syncthreads();
    }
    if (tid == 0) g_part[blk] = red[0];
}

// ---------------------------------------------------------------------------
// Kernel 4: final loss reduction
// ---------------------------------------------------------------------------
__global__ void finish_loss_kernel(float* __restrict__ out) {
    __shared__ double red[256];
    double s = 0.0;
    for (int i = threadIdx.x; i < NTILES; i += 256) s += g_part[i];
    red[threadIdx.x] = s;
    __syncthreads();
    #pragma unroll
    for (int st = 128; st > 0; st >>= 1) {
        if (threadIdx.x < st) red[threadIdx.x] += red[threadIdx.x + st];
        __syncthreads();
    }
    if (threadIdx.x == 0) {
        double mean = red[0] / (double)((size_t)B_ * D_ * T_);
        out[(size_t)B_ * D_ * T_ + BT_] = (float)(mean * 0.25);
    }
}

// ---------------------------------------------------------------------------
extern "C" void kernel_launch(void* const* d_in, const int* in_sizes, int n_in,
                              void* d_out, int out_size) {
    const float* x = (const float*)d_in[0];   // (B, D, T) fp32
    const float* W = (const float*)d_in[1];   // (K, D)    fp32
    float* out = (float*)d_out;               // [quantized | indices | loss]

    cudaFuncSetAttribute(hmma_pass1_kernel, cudaFuncAttributeMaxDynamicSharedMemorySize, SM1_TOT);
    cudaFuncSetAttribute(pass2_fused_kernel, cudaFuncAttributeMaxDynamicSharedMemorySize, SM3_TOT);

    prep_w_kernel<<<K_ / 8, dim3(32, 8)>>>(W);
    hmma_pass1_kernel<<<NTILES, 128, SM1_TOT>>>(x);
    pass2_fused_kernel<<<NTILES, 256, SM3_TOT>>>(x, W, out, out + (size_t)B_ * D_ * T_);
    finish_loss_kernel<<<1, 256>>>(out);
}

// round 7
// speedup vs baseline: 1.9262x; 1.1719x over previous
#include <cuda_runtime.h>
#include <cuda_bf16.h>
#include <cstdint>

// Problem constants (fixed by the dataset)
#define B_  16
#define D_  128
#define T_  4096
#define K_  1024
#define BT_ (B_*T_)          // 65536 rows
#define NT1 (BT_/128)        // 512 pass1 tiles
#define NT2 (BT_/64)         // 1024 pass2 tiles
#define NCAND 6
#define DELTA 3e-4f
#define APITCHB 272          // smem MMA tile row pitch (136 bf16)
#define P2P 68               // pass2 smem pitch in floats (272B, 16B-aligned)

// ---------------------------------------------------------------------------
// Device scratch
// ---------------------------------------------------------------------------
__device__ float  g_wnorm[K_];                           // fl32(||w||^2)
__device__ __align__(16) __nv_bfloat16 g_Wb[K_ * D_];    // bf16 codebook [k][d]
__device__ float  g_candv[BT_ * NCAND];
__device__ int    g_candk[BT_ * NCAND];
__device__ double g_part[NT2];

__device__ __forceinline__ uint32_t smem_u32(const void* p) {
    uint32_t a;
    asm("{ .reg .u64 t; cvta.to.shared.u64 t, %1; cvt.u32.u64 %0, t; }" : "=r"(a) : "l"(p));
    return a;
}

// ascending top-6 (strict < keeps earlier/lower-k entry on ties)
__device__ __forceinline__ void insert6(float v, int k, float* cv, int* ck) {
    if (v < cv[5]) {
        cv[5] = v; ck[5] = k;
        #pragma unroll
        for (int a = 5; a > 0; a--) {
            bool sw = cv[a] < cv[a - 1];
            float tv = sw ? cv[a] : cv[a - 1];
            float tu = sw ? cv[a - 1] : cv[a];
            int   tk = sw ? ck[a] : ck[a - 1];
            int   tl = sw ? ck[a - 1] : ck[a];
            cv[a - 1] = tv; cv[a] = tu;
            ck[a - 1] = tk; ck[a] = tl;
        }
    }
}

// ---------------------------------------------------------------------------
// Kernel 1: ||w||^2 (fp64->fp32, correctly rounded) + bf16 codebook.
// ---------------------------------------------------------------------------
__global__ void prep_w_kernel(const float* __restrict__ W) {
    int k = blockIdx.x * 8 + threadIdx.y;
    int lane = threadIdx.x;
    float4 v = *(const float4*)(W + (size_t)k * D_ + lane * 4);
    __nv_bfloat16 b4[4] = { __float2bfloat16(v.x), __float2bfloat16(v.y),
                            __float2bfloat16(v.z), __float2bfloat16(v.w) };
    *(uint2*)(g_Wb + (size_t)k * D_ + lane * 4) = *(uint2*)b4;
    double s = (double)v.x * v.x + (double)v.y * v.y
             + (double)v.z * v.z + (double)v.w * v.w;
    #pragma unroll
    for (int o = 16; o > 0; o >>= 1) s += __shfl_down_sync(0xffffffffu, s, o);
    if (lane == 0) g_wnorm[k] = (float)s;
}

// ---------------------------------------------------------------------------
// Kernel 2: HMMA pass-1 (fused x->bf16): approx scores + per-row top-6.
// 256 threads = 8 warps x 16 rows. A frags register-resident for whole CTA.
// np-outer / ks-inner keeps only 8 live accumulators -> no spills.
// ---------------------------------------------------------------------------
#define SM1_A   0
#define SM1_R2  34816
#define SM1_TOT (34816 + 65536)

__global__ void __launch_bounds__(256, 2) hmma_pass1_kernel(const float* __restrict__ x) {
    extern __shared__ char smem[];
    char* sA = smem + SM1_A;
    char* r2 = smem + SM1_R2;
    float* xs  = (float*)r2;                    // [128 d][128 t] fp32 staging
    char*  sB  = r2;                            // [128 n][272B] after conversion
    float* wns = (float*)(r2 + 34816);          // [1024]
    int tid = threadIdx.x;
    int warp = tid >> 5, lane = tid & 31;
    int blk = blockIdx.x;
    int b = blk >> 5, t0 = (blk & 31) * 128, r0 = blk * 128;

    // --- stage x tile fp32 (coalesced along t) ---
    const float* xb = x + (size_t)b * D_ * T_ + t0;
    #pragma unroll
    for (int i = 0; i < 16; i++) {
        int lin = i * 256 + tid;
        int d = lin >> 5, t4 = lin & 31;
        *(float4*)(xs + d * 128 + t4 * 4) = *(const float4*)(xb + (size_t)d * T_ + t4 * 4);
    }
    __syncthreads();
    // --- transpose-convert to bf16 A tile: sA[row=t][d] ---
    {
        int m = tid >> 1, half = tid & 1;
        #pragma unroll
        for (int cc = 0; cc < 8; cc++) {
            int c = half * 8 + cc;
            __nv_bfloat16 tmp[8];
            #pragma unroll
            for (int j = 0; j < 8; j++) tmp[j] = __float2bfloat16(xs[(c * 8 + j) * 128 + m]);
            *(uint4*)(sA + m * APITCHB + c * 16) = *(uint4*)tmp;
        }
    }
    __syncthreads();
    #pragma unroll
    for (int i = 0; i < 4; i++) wns[i * 256 + tid] = g_wnorm[i * 256 + tid];

    uint32_t sAu = smem_u32(sA), sBu = smem_u32(sB);
    uint32_t aBase = sAu + (warp * 16 + (lane & 15)) * APITCHB + (lane >> 4) * 16;
    uint32_t bRowOff = ((lane & 7) + (lane >> 4) * 8) * APITCHB + ((lane >> 3) & 1) * 16;

    // A fragments: loaded ONCE, register-resident (rows fixed per warp)
    uint32_t af[8][4];
    #pragma unroll
    for (int ks = 0; ks < 8; ks++)
        asm volatile("ldmatrix.sync.aligned.m8n8.x4.shared.b16 {%0,%1,%2,%3}, [%4];"
            : "=r"(af[ks][0]), "=r"(af[ks][1]), "=r"(af[ks][2]), "=r"(af[ks][3])
            : "r"(aBase + ks * 32));

    float cv0[NCAND], cv1[NCAND]; int ck0[NCAND], ck1[NCAND];
    #pragma unroll
    for (int a = 0; a < NCAND; a++) {
        cv0[a] = 3.4e38f; cv1[a] = 3.4e38f; ck0[a] = 0; ck1[a] = 0;
    }

    for (int kt = 0; kt < 8; kt++) {
        __syncthreads();   // prev readers of sB done
        const uint4* gb = (const uint4*)(g_Wb + (size_t)kt * 128 * D_);
        #pragma unroll
        for (int i = 0; i < 8; i++) {
            int s = i * 256 + tid;
            int row = s >> 4, c = s & 15;
            *(uint4*)(sB + row * APITCHB + c * 16) = gb[s];
        }
        __syncthreads();

        #pragma unroll
        for (int np = 0; np < 8; np++) {
            float acc[2][4];
            #pragma unroll
            for (int h = 0; h < 2; h++)
                #pragma unroll
                for (int q = 0; q < 4; q++) acc[h][q] = 0.f;

            #pragma unroll
            for (int ks = 0; ks < 8; ks++) {
                uint32_t b0, b1, b2, b3;
                uint32_t baddr = sBu + np * 16 * APITCHB + ks * 32 + bRowOff;
                asm volatile("ldmatrix.sync.aligned.m8n8.x4.shared.b16 {%0,%1,%2,%3}, [%4];"
                    : "=r"(b0), "=r"(b1), "=r"(b2), "=r"(b3) : "r"(baddr));
                asm volatile("mma.sync.aligned.m16n8k16.row.col.f32.bf16.bf16.f32 "
                    "{%0,%1,%2,%3}, {%4,%5,%6,%7}, {%8,%9}, {%0,%1,%2,%3};"
                    : "+f"(acc[0][0]), "+f"(acc[0][1]), "+f"(acc[0][2]), "+f"(acc[0][3])
                    : "r"(af[ks][0]), "r"(af[ks][1]), "r"(af[ks][2]), "r"(af[ks][3]),
                      "r"(b0), "r"(b1));
                asm volatile("mma.sync.aligned.m16n8k16.row.col.f32.bf16.bf16.f32 "
                    "{%0,%1,%2,%3}, {%4,%5,%6,%7}, {%8,%9}, {%0,%1,%2,%3};"
                    : "+f"(acc[1][0]), "+f"(acc[1][1]), "+f"(acc[1][2]), "+f"(acc[1][3])
                    : "r"(af[ks][0]), "r"(af[ks][1]), "r"(af[ks][2]), "r"(af[ks][3]),
                      "r"(b2), "r"(b3));
            }

            // scores: v = wn_k - 2*dot
            // list0: row warp*16 + (lane>>2); list1: row +8
            #pragma unroll
            for (int h = 0; h < 2; h++) {
                int k0 = kt * 128 + np * 16 + h * 8 + 2 * (lane & 3);
                float2 wnp = *(const float2*)(wns + k0);
                insert6(fmaf(-2.0f, acc[h][0], wnp.x), k0,     cv0, ck0);
                insert6(fmaf(-2.0f, acc[h][1], wnp.y), k0 + 1, cv0, ck0);
                insert6(fmaf(-2.0f, acc[h][2], wnp.x), k0,     cv1, ck1);
                insert6(fmaf(-2.0f, acc[h][3], wnp.y), k0 + 1, cv1, ck1);
            }
        }
    }

    // merge: 4 threads per row -> top-6 per row (reuse r2 region)
    __syncthreads();
    float* mv = (float*)r2;                      // [128][24]
    int*   mk = (int*)(r2 + 128 * 24 * 4);       // [128][24]
    {
        int row0 = warp * 16 + (lane >> 2);
        int q = lane & 3;
        #pragma unroll
        for (int a = 0; a < NCAND; a++) {
            mv[row0 * 24 + q * 6 + a] = cv0[a];  mk[row0 * 24 + q * 6 + a] = ck0[a];
            mv[(row0 + 8) * 24 + q * 6 + a] = cv1[a];  mk[(row0 + 8) * 24 + q * 6 + a] = ck1[a];
        }
    }
    __syncthreads();
    if (tid < 128) {
        float bv[NCAND]; int bk[NCAND];
        #pragma unroll
        for (int a = 0; a < NCAND; a++) { bv[a] = 3.4e38f; bk[a] = 0; }
        #pragma unroll
        for (int i = 0; i < 24; i++)
            insert6(mv[tid * 24 + i], mk[tid * 24 + i], bv, bk);
        int r = r0 + tid;
        #pragma unroll
        for (int a = 0; a < NCAND; a++) {
            g_candv[r * NCAND + a] = bv[a];
            g_candk[r * NCAND + a] = bk[a];
        }
    }
}

// ---------------------------------------------------------------------------
// Kernel 3: fused exact-resolve + gather + output + loss. 64-t tiles, 256 thr.
// smem pitch P2P=68 floats (272B, 16B-aligned vector rows).
// ---------------------------------------------------------------------------
#define P2T      64
#define SM3_XS   0
#define SM3_QS   (128 * P2P * 4)                 // 34816
#define SM3_IDX  (SM3_QS + 128 * P2P * 4)        // 69632
#define SM3_RED  (SM3_IDX + 256)
#define SM3_TOT  (SM3_RED + 2048)

__global__ void __launch_bounds__(256) pass2_fused_kernel(const float* __restrict__ x,
        const float* __restrict__ W, float* __restrict__ out, float* __restrict__ out_idx_f) {
    extern __shared__ char smem[];
    float* xs = (float*)(smem + SM3_XS);     // [128 d][P2P]
    float* qs = (float*)(smem + SM3_QS);     // [128 d][P2P]
    int* idxs = (int*)(smem + SM3_IDX);
    double* red = (double*)(smem + SM3_RED);
    int tid = threadIdx.x;
    int blk = blockIdx.x;
    int b = blk >> 6, t0 = (blk & 63) * P2T, r0 = blk * P2T;

    const float* xb = x + (size_t)b * D_ * T_ + t0;
    #pragma unroll
    for (int i = 0; i < 8; i++) {
        int lin = i * 256 + tid;
        int d = lin >> 4, t4 = lin & 15;
        *(float4*)(xs + d * P2P + t4 * 4) = *(const float4*)(xb + (size_t)d * T_ + t4 * 4);
    }
    __syncthreads();

    if (tid < P2T) {
        int t = tid, r = r0 + tid;
        // xnorm: double accumulate, round once (whole-ulp-shift invariant)
        double sn = 0.0;
        #pragma unroll 8
        for (int d = 0; d < D_; d++) { float v = xs[d * P2P + t]; sn += (double)v * (double)v; }
        float xn = (float)sn;

        float cvl[NCAND]; int ckl[NCAND];
        #pragma unroll
        for (int a = 0; a < NCAND; a++) { cvl[a] = g_candv[r * NCAND + a]; ckl[a] = g_candk[r * NCAND + a]; }
        float lim = cvl[0] + DELTA;
        float bv = 3.4e38f; int bi = 0x7fffffff;
        if (cvl[NCAND - 1] <= lim) {
            // candidate overflow (p~0): exact full scan, ascending k
            for (int k = 0; k < K_; k++) {
                float acc = 0.f;
                const float* w = W + (size_t)k * D_;
                for (int d = 0; d < D_; d++) acc = fmaf(xs[d * P2P + t], w[d], acc);
                float v = __fsub_rn(__fadd_rn(xn, g_wnorm[k]), 2.0f * acc);
                if (v < bv) { bv = v; bi = k; }
            }
        } else {
            #pragma unroll
            for (int a = 0; a < NCAND; a++) {
                if (cvl[a] <= lim) {
                    int k = ckl[a];
                    float acc = 0.f;
                    const float* w = W + (size_t)k * D_;
                    #pragma unroll 8
                    for (int d = 0; d < D_; d++) acc = fmaf(xs[d * P2P + t], w[d], acc);
                    float v = __fsub_rn(__fadd_rn(xn, g_wnorm[k]), 2.0f * acc);
                    if (v < bv || (v == bv && k < bi)) { bv = v; bi = k; }
                }
            }
        }
        idxs[t] = bi;
        out_idx_f[r] = (float)bi;
    }
    __syncthreads();

    // gather W rows -> qs[d][t]  (lanes vary row -> conflict-free)
    #pragma unroll
    for (int i = 0; i < 8; i++) {
        int s = i * 256 + tid;            // 0..2047
        int row = s & 63, c4 = s >> 6;    // c4 0..31
        float4 q = *(const float4*)(W + (size_t)idxs[row] * D_ + c4 * 4);
        qs[(c4 * 4 + 0) * P2P + row] = q.x;
        qs[(c4 * 4 + 1) * P2P + row] = q.y;
        qs[(c4 * 4 + 2) * P2P + row] = q.z;
        qs[(c4 * 4 + 3) * P2P + row] = q.w;
    }
    __syncthreads();

    // write out (coalesced along t) + loss
    double lsum = 0.0;
    int t = tid & 63, dg = tid >> 6;
    float* ob = out + (size_t)b * D_ * T_ + t0;
    #pragma unroll 8
    for (int p = 0; p < 32; p++) {
        int d = dg * 32 + p;
        float xv = xs[d * P2P + t];
        float q  = qs[d * P2P + t];
        float df = __fsub_rn(q, xv);
        ob[(size_t)d * T_ + t] = __fadd_rn(xv, df);
        float sq = __fmul_rn(df, df);
        lsum += (double)sq;
    }
    red[tid] = lsum;
    __syncthreads();
    #pragma unroll
    for (int s = 128; s > 0; s >>= 1) {
        if (tid < s) red[tid] += red[tid + s];
        __syncthreads();
    }
    if (tid == 0) g_part[blk] = red[0];
}

// ---------------------------------------------------------------------------
// Kernel 4: final loss reduction
// ---------------------------------------------------------------------------
__global__ void finish_loss_kernel(float* __restrict__ out) {
    __shared__ double red[256];
    double s = 0.0;
    for (int i = threadIdx.x; i < NT2; i += 256) s += g_part[i];
    red[threadIdx.x] = s;
    __syncthreads();
    #pragma unroll
    for (int st = 128; st > 0; st >>= 1) {
        if (threadIdx.x < st) red[threadIdx.x] += red[threadIdx.x + st];
        __syncthreads();
    }
    if (threadIdx.x == 0) {
        double mean = red[0] / (double)((size_t)B_ * D_ * T_);
        out[(size_t)B_ * D_ * T_ + BT_] = (float)(mean * 0.25);
    }
}

// ---------------------------------------------------------------------------
extern "C" void kernel_launch(void* const* d_in, const int* in_sizes, int n_in,
                              void* d_out, int out_size) {
    const float* x = (const float*)d_in[0];   // (B, D, T) fp32
    const float* W = (const float*)d_in[1];   // (K, D)    fp32
    float* out = (float*)d_out;               // [quantized | indices | loss]

    cudaFuncSetAttribute(hmma_pass1_kernel, cudaFuncAttributeMaxDynamicSharedMemorySize, SM1_TOT);
    cudaFuncSetAttribute(pass2_fused_kernel, cudaFuncAttributeMaxDynamicSharedMemorySize, SM3_TOT);

    prep_w_kernel<<<K_ / 8, dim3(32, 8)>>>(W);
    hmma_pass1_kernel<<<NT1, 256, SM1_TOT>>>(x);
    pass2_fused_kernel<<<NT2, 256, SM3_TOT>>>(x, W, out, out + (size_t)B_ * D_ * T_);
    finish_loss_kernel<<<1, 256>>>(out);
}

// round 8
// speedup vs baseline: 1.9409x; 1.0076x over previous
#include <cuda_runtime.h>
#include <cuda_bf16.h>
#include <cstdint>

// Problem constants (fixed by the dataset)
#define B_  16
#define D_  128
#define T_  4096
#define K_  1024
#define BT_ (B_*T_)          // 65536 rows
#define R1  256              // pass1 rows per CTA
#define NT1 (BT_/R1)         // 256 pass1 tiles
#define NT2 (BT_/64)         // 1024 pass2 tiles
#define NCAND 6
#define DELTA 3e-4f
#define APITCHB 272          // smem MMA tile row pitch (136 bf16)
#define P2P 68               // pass2 smem pitch in floats (272B)

// ---------------------------------------------------------------------------
// Device scratch
// ---------------------------------------------------------------------------
__device__ float  g_wnorm[K_];                           // fl32(||w||^2)
__device__ __align__(16) __nv_bfloat16 g_Wb[K_ * D_];    // bf16 codebook [k][d]
__device__ float  g_candv[BT_ * NCAND];
__device__ int    g_candk[BT_ * NCAND];
__device__ double g_part[NT2];

__device__ __forceinline__ uint32_t smem_u32(const void* p) {
    uint32_t a;
    asm("{ .reg .u64 t; cvta.to.shared.u64 t, %1; cvt.u32.u64 %0, t; }" : "=r"(a) : "l"(p));
    return a;
}
__device__ __forceinline__ void cp_async16(uint32_t dst, const void* src) {
    asm volatile("cp.async.cg.shared.global [%0], [%1], 16;" :: "r"(dst), "l"(src));
}
#define CP_COMMIT() asm volatile("cp.async.commit_group;" ::: "memory")
#define CP_WAIT(N)  asm volatile("cp.async.wait_group %0;" :: "n"(N) : "memory")

// ascending top-6 (strict < keeps earlier/lower-k entry on ties)
__device__ __forceinline__ void insert6(float v, int k, float* cv, int* ck) {
    if (v < cv[5]) {
        cv[5] = v; ck[5] = k;
        #pragma unroll
        for (int a = 5; a > 0; a--) {
            bool sw = cv[a] < cv[a - 1];
            float tv = sw ? cv[a] : cv[a - 1];
            float tu = sw ? cv[a - 1] : cv[a];
            int   tk = sw ? ck[a] : ck[a - 1];
            int   tl = sw ? ck[a - 1] : ck[a];
            cv[a - 1] = tv; cv[a] = tu;
            ck[a - 1] = tk; ck[a] = tl;
        }
    }
}

// ---------------------------------------------------------------------------
// Kernel 1: ||w||^2 (fp64->fp32, correctly rounded) + bf16 codebook.
// ---------------------------------------------------------------------------
__global__ void prep_w_kernel(const float* __restrict__ W) {
    int k = blockIdx.x * 8 + threadIdx.y;
    int lane = threadIdx.x;
    float4 v = *(const float4*)(W + (size_t)k * D_ + lane * 4);
    __nv_bfloat16 b4[4] = { __float2bfloat16(v.x), __float2bfloat16(v.y),
                            __float2bfloat16(v.z), __float2bfloat16(v.w) };
    *(uint2*)(g_Wb + (size_t)k * D_ + lane * 4) = *(uint2*)b4;
    double s = (double)v.x * v.x + (double)v.y * v.y
             + (double)v.z * v.z + (double)v.w * v.w;
    #pragma unroll
    for (int o = 16; o > 0; o >>= 1) s += __shfl_down_sync(0xffffffffu, s, o);
    if (lane == 0) g_wnorm[k] = (float)s;
}

// ---------------------------------------------------------------------------
// Kernel 2: HMMA pass-1 v3: 512 threads / 16 warps, 256-row tile, cp.async
// double-buffered B. A frags register-resident. Approx scores + top-6.
// smem: sA[256x272] | sB0[128x272] | sB1[128x272] | wns[1024]
// ---------------------------------------------------------------------------
#define SM_A    0
#define SM_B0   69632
#define SM_B1   (69632 + 34816)
#define SM_WNS  (69632 + 69632)
#define SM1_TOT (69632 + 69632 + 4096)   // 143,360

__global__ void __launch_bounds__(512, 1) hmma_pass1_kernel(const float* __restrict__ x) {
    extern __shared__ char smem[];
    char* sA = smem + SM_A;
    float* wns = (float*)(smem + SM_WNS);
    int tid = threadIdx.x;
    int warp = tid >> 5, lane = tid & 31;
    int blk = blockIdx.x;
    int b = blk >> 4, t0 = (blk & 15) * R1, r0 = blk * R1;

    // --- A tile: two 128-t halves, fp32 staged in the B-buffer area, then
    //     transpose-converted into sA[row=t][d] (bf16, 272B pitch) ---
    float* xs = (float*)(smem + SM_B0);          // 64KB staging (spans B0+B1)
    const float* xb = x + (size_t)b * D_ * T_ + t0;
    #pragma unroll
    for (int h = 0; h < 2; h++) {
        __syncthreads();
        #pragma unroll
        for (int i = 0; i < 8; i++) {
            int lin = i * 512 + tid;             // 4096 float4 slots
            int d = lin >> 5, t4 = lin & 31;
            *(float4*)(xs + d * 128 + t4 * 4) =
                *(const float4*)(xb + (size_t)d * T_ + h * 128 + t4 * 4);
        }
        __syncthreads();
        int m = tid & 127;                       // t within half (lanes vary m)
        int cq = tid >> 7;                       // 0..3
        #pragma unroll
        for (int cc = 0; cc < 4; cc++) {
            int c = cq * 4 + cc;                 // 16B chunk 0..15
            __nv_bfloat16 tmp[8];
            #pragma unroll
            for (int j = 0; j < 8; j++) tmp[j] = __float2bfloat16(xs[(c * 8 + j) * 128 + m]);
            *(uint4*)(sA + (h * 128 + m) * APITCHB + c * 16) = *(uint4*)tmp;
        }
    }
    __syncthreads();
    wns[tid] = g_wnorm[tid];
    wns[512 + tid] = g_wnorm[512 + tid];

    uint32_t sAu = smem_u32(sA);
    uint32_t sB0u = smem_u32(smem + SM_B0), sB1u = smem_u32(smem + SM_B1);
    uint32_t aBase = sAu + (warp * 16 + (lane & 15)) * APITCHB + (lane >> 4) * 16;
    uint32_t bRowOff = ((lane & 7) + (lane >> 4) * 8) * APITCHB + ((lane >> 3) & 1) * 16;

    // A fragments: loaded ONCE, register-resident (16 rows per warp)
    uint32_t af[8][4];
    #pragma unroll
    for (int ks = 0; ks < 8; ks++)
        asm volatile("ldmatrix.sync.aligned.m8n8.x4.shared.b16 {%0,%1,%2,%3}, [%4];"
            : "=r"(af[ks][0]), "=r"(af[ks][1]), "=r"(af[ks][2]), "=r"(af[ks][3])
            : "r"(aBase + ks * 32));

    float cv0[NCAND], cv1[NCAND]; int ck0[NCAND], ck1[NCAND];
    #pragma unroll
    for (int a = 0; a < NCAND; a++) {
        cv0[a] = 3.4e38f; cv1[a] = 3.4e38f; ck0[a] = 0; ck1[a] = 0;
    }

    // prologue: async-stage B k-tile 0 into buf0
    {
        uint32_t dst = sB0u;
        const __nv_bfloat16* src = g_Wb;
        #pragma unroll
        for (int i = 0; i < 4; i++) {
            int s = i * 512 + tid;               // 2048 16B chunks
            int row = s >> 4, c = s & 15;
            cp_async16(dst + row * APITCHB + c * 16, src + (size_t)row * D_ + c * 8);
        }
        CP_COMMIT();
    }

    for (int kt = 0; kt < 8; kt++) {
        if (kt < 7) {   // prefetch next k-tile into the other buffer
            uint32_t dst = ((kt + 1) & 1) ? sB1u : sB0u;
            const __nv_bfloat16* src = g_Wb + (size_t)(kt + 1) * 128 * D_;
            #pragma unroll
            for (int i = 0; i < 4; i++) {
                int s = i * 512 + tid;
                int row = s >> 4, c = s & 15;
                cp_async16(dst + row * APITCHB + c * 16, src + (size_t)row * D_ + c * 8);
            }
            CP_COMMIT();
            CP_WAIT(1);
        } else {
            CP_WAIT(0);
        }
        __syncthreads();
        uint32_t sBu = (kt & 1) ? sB1u : sB0u;

        #pragma unroll
        for (int np = 0; np < 8; np++) {
            float acc[2][4];
            #pragma unroll
            for (int h = 0; h < 2; h++)
                #pragma unroll
                for (int q = 0; q < 4; q++) acc[h][q] = 0.f;

            #pragma unroll
            for (int ks = 0; ks < 8; ks++) {
                uint32_t b0, b1, b2, b3;
                uint32_t baddr = sBu + np * 16 * APITCHB + ks * 32 + bRowOff;
                asm volatile("ldmatrix.sync.aligned.m8n8.x4.shared.b16 {%0,%1,%2,%3}, [%4];"
                    : "=r"(b0), "=r"(b1), "=r"(b2), "=r"(b3) : "r"(baddr));
                asm volatile("mma.sync.aligned.m16n8k16.row.col.f32.bf16.bf16.f32 "
                    "{%0,%1,%2,%3}, {%4,%5,%6,%7}, {%8,%9}, {%0,%1,%2,%3};"
                    : "+f"(acc[0][0]), "+f"(acc[0][1]), "+f"(acc[0][2]), "+f"(acc[0][3])
                    : "r"(af[ks][0]), "r"(af[ks][1]), "r"(af[ks][2]), "r"(af[ks][3]),
                      "r"(b0), "r"(b1));
                asm volatile("mma.sync.aligned.m16n8k16.row.col.f32.bf16.bf16.f32 "
                    "{%0,%1,%2,%3}, {%4,%5,%6,%7}, {%8,%9}, {%0,%1,%2,%3};"
                    : "+f"(acc[1][0]), "+f"(acc[1][1]), "+f"(acc[1][2]), "+f"(acc[1][3])
                    : "r"(af[ks][0]), "r"(af[ks][1]), "r"(af[ks][2]), "r"(af[ks][3]),
                      "r"(b2), "r"(b3));
            }

            // scores: v = wn_k - 2*dot; list0 row warp*16+(lane>>2), list1 +8
            #pragma unroll
            for (int h = 0; h < 2; h++) {
                int k0 = kt * 128 + np * 16 + h * 8 + 2 * (lane & 3);
                float2 wnp = *(const float2*)(wns + k0);
                insert6(fmaf(-2.0f, acc[h][0], wnp.x), k0,     cv0, ck0);
                insert6(fmaf(-2.0f, acc[h][1], wnp.y), k0 + 1, cv0, ck0);
                insert6(fmaf(-2.0f, acc[h][2], wnp.x), k0,     cv1, ck1);
                insert6(fmaf(-2.0f, acc[h][3], wnp.y), k0 + 1, cv1, ck1);
            }
        }
        __syncthreads();   // all warps done with this buffer before re-stage
    }

    // merge: 4 threads per row -> top-6 per row. Reuse sA region.
    float* mv = (float*)smem;                    // [256][24]
    int*   mk = (int*)(smem + 256 * 24 * 4);     // [256][24]
    __syncthreads();
    {
        int row0 = warp * 16 + (lane >> 2);
        int q = lane & 3;
        #pragma unroll
        for (int a = 0; a < NCAND; a++) {
            mv[row0 * 24 + q * 6 + a] = cv0[a];  mk[row0 * 24 + q * 6 + a] = ck0[a];
            mv[(row0 + 8) * 24 + q * 6 + a] = cv1[a];  mk[(row0 + 8) * 24 + q * 6 + a] = ck1[a];
        }
    }
    __syncthreads();
    if (tid < 256) {
        float bv[NCAND]; int bk[NCAND];
        #pragma unroll
        for (int a = 0; a < NCAND; a++) { bv[a] = 3.4e38f; bk[a] = 0; }
        #pragma unroll
        for (int i = 0; i < 24; i++)
            insert6(mv[tid * 24 + i], mk[tid * 24 + i], bv, bk);
        int r = r0 + tid;
        #pragma unroll
        for (int a = 0; a < NCAND; a++) {
            g_candv[r * NCAND + a] = bv[a];
            g_candk[r * NCAND + a] = bk[a];
        }
    }
}

// ---------------------------------------------------------------------------
// Kernel 3: fused exact-resolve + gather + output + loss. 64-t tiles, 256 thr.
// ---------------------------------------------------------------------------
#define P2T      64
#define SM3_XS   0
#define SM3_QS   (128 * P2P * 4)                 // 34816
#define SM3_IDX  (SM3_QS + 128 * P2P * 4)        // 69632
#define SM3_RED  (SM3_IDX + 256)
#define SM3_TOT  (SM3_RED + 2048)

__global__ void __launch_bounds__(256) pass2_fused_kernel(const float* __restrict__ x,
        const float* __restrict__ W, float* __restrict__ out, float* __restrict__ out_idx_f) {
    extern __shared__ char smem[];
    float* xs = (float*)(smem + SM3_XS);     // [128 d][P2P]
    float* qs = (float*)(smem + SM3_QS);     // [128 d][P2P]
    int* idxs = (int*)(smem + SM3_IDX);
    double* red = (double*)(smem + SM3_RED);
    int tid = threadIdx.x;
    int blk = blockIdx.x;
    int b = blk >> 6, t0 = (blk & 63) * P2T, r0 = blk * P2T;

    const float* xb = x + (size_t)b * D_ * T_ + t0;
    #pragma unroll
    for (int i = 0; i < 8; i++) {
        int lin = i * 256 + tid;
        int d = lin >> 4, t4 = lin & 15;
        *(float4*)(xs + d * P2P + t4 * 4) = *(const float4*)(xb + (size_t)d * T_ + t4 * 4);
    }
    __syncthreads();

    if (tid < P2T) {
        int t = tid, r = r0 + tid;
        // xnorm: double accumulate, round once (whole-ulp-shift invariant)
        double sn = 0.0;
        #pragma unroll 8
        for (int d = 0; d < D_; d++) { float v = xs[d * P2P + t]; sn += (double)v * (double)v; }
        float xn = (float)sn;

        float cvl[NCAND]; int ckl[NCAND];
        #pragma unroll
        for (int a = 0; a < NCAND; a++) { cvl[a] = g_candv[r * NCAND + a]; ckl[a] = g_candk[r * NCAND + a]; }
        float lim = cvl[0] + DELTA;
        float bv = 3.4e38f; int bi = 0x7fffffff;
        if (cvl[NCAND - 1] <= lim) {
            // candidate overflow (p~0): exact full scan, ascending k
            for (int k = 0; k < K_; k++) {
                float acc = 0.f;
                const float* w = W + (size_t)k * D_;
                for (int d = 0; d < D_; d++) acc = fmaf(xs[d * P2P + t], w[d], acc);
                float v = __fsub_rn(__fadd_rn(xn, g_wnorm[k]), 2.0f * acc);
                if (v < bv) { bv = v; bi = k; }
            }
        } else {
            #pragma unroll
            for (int a = 0; a < NCAND; a++) {
                if (cvl[a] <= lim) {
                    int k = ckl[a];
                    float acc = 0.f;
                    const float* w = W + (size_t)k * D_;
                    #pragma unroll 8
                    for (int d = 0; d < D_; d++) acc = fmaf(xs[d * P2P + t], w[d], acc);
                    float v = __fsub_rn(__fadd_rn(xn, g_wnorm[k]), 2.0f * acc);
                    if (v < bv || (v == bv && k < bi)) { bv = v; bi = k; }
                }
            }
        }
        idxs[t] = bi;
        out_idx_f[r] = (float)bi;
    }
    __syncthreads();

    // gather W rows -> qs[d][t]
    #pragma unroll
    for (int i = 0; i < 8; i++) {
        int s = i * 256 + tid;            // 0..2047
        int row = s & 63, c4 = s >> 6;    // c4 0..31
        float4 q = *(const float4*)(W + (size_t)idxs[row] * D_ + c4 * 4);
        qs[(c4 * 4 + 0) * P2P + row] = q.x;
        qs[(c4 * 4 + 1) * P2P + row] = q.y;
        qs[(c4 * 4 + 2) * P2P + row] = q.z;
        qs[(c4 * 4 + 3) * P2P + row] = q.w;
    }
    __syncthreads();

    // write out (coalesced along t) + loss
    double lsum = 0.0;
    int t = tid & 63, dg = tid >> 6;
    float* ob = out + (size_t)b * D_ * T_ + t0;
    #pragma unroll 8
    for (int p = 0; p < 32; p++) {
        int d = dg * 32 + p;
        float xv = xs[d * P2P + t];
        float q  = qs[d * P2P + t];
        float df = __fsub_rn(q, xv);
        ob[(size_t)d * T_ + t] = __fadd_rn(xv, df);
        float sq = __fmul_rn(df, df);
        lsum += (double)sq;
    }
    red[tid] = lsum;
    __syncthreads();
    #pragma unroll
    for (int s = 128; s > 0; s >>= 1) {
        if (tid < s) red[tid] += red[tid + s];
        __syncthreads();
    }
    if (tid == 0) g_part[blk] = red[0];
}

// ---------------------------------------------------------------------------
// Kernel 4: final loss reduction
// ---------------------------------------------------------------------------
__global__ void finish_loss_kernel(float* __restrict__ out) {
    __shared__ double red[256];
    double s = 0.0;
    for (int i = threadIdx.x; i < NT2; i += 256) s += g_part[i];
    red[threadIdx.x] = s;
    __syncthreads();
    #pragma unroll
    for (int st = 128; st > 0; st >>= 1) {
        if (threadIdx.x < st) red[threadIdx.x] += red[threadIdx.x + st];
        __syncthreads();
    }
    if (threadIdx.x == 0) {
        double mean = red[0] / (double)((size_t)B_ * D_ * T_);
        out[(size_t)B_ * D_ * T_ + BT_] = (float)(mean * 0.25);
    }
}

// ---------------------------------------------------------------------------
extern "C" void kernel_launch(void* const* d_in, const int* in_sizes, int n_in,
                              void* d_out, int out_size) {
    const float* x = (const float*)d_in[0];   // (B, D, T) fp32
    const float* W = (const float*)d_in[1];   // (K, D)    fp32
    float* out = (float*)d_out;               // [quantized | indices | loss]

    cudaFuncSetAttribute(hmma_pass1_kernel, cudaFuncAttributeMaxDynamicSharedMemorySize, SM1_TOT);
    cudaFuncSetAttribute(pass2_fused_kernel, cudaFuncAttributeMaxDynamicSharedMemorySize, SM3_TOT);

    prep_w_kernel<<<K_ / 8, dim3(32, 8)>>>(W);
    hmma_pass1_kernel<<<NT1, 512, SM1_TOT>>>(x);
    pass2_fused_kernel<<<NT2, 256, SM3_TOT>>>(x, W, out, out + (size_t)B_ * D_ * T_);
    finish_loss_kernel<<<1, 256>>>(out);
}